// round 15
// baseline (speedup 1.0000x reference)
#include <cuda_runtime.h>
#include <math.h>
#include <stdint.h>

// Problem constants
#define NB   2
#define NS   2048
#define ND   2048
#define NH   16
#define NDH  128
#define MROWS (NB*NS)        // 4096 flattened (b,s) rows
#define FEAT  (NH*NDH)       // 2048 flattened (h,e) features

// Scratch buffers (allocation-free rule: __device__ globals)
#define QKV_ELEMS 8388608ull  // 4096 * 2048
__device__ float g_q[QKV_ELEMS];
__device__ float g_k[QKV_ELEMS];
__device__ float g_v[QKV_ELEMS];
__device__ float g_z[QKV_ELEMS];

// ---------------------------------------------------------------------------
// tf32 helpers (flash path, unchanged from R13)
// ---------------------------------------------------------------------------
__device__ __forceinline__ void split_tf32(float x, uint32_t& hi, uint32_t& lo)
{
    uint32_t h;
    asm("cvt.rna.tf32.f32 %0, %1;" : "=r"(h) : "f"(x));
    lo = __float_as_uint(x - __uint_as_float(h));
    hi = h;
}

__device__ __forceinline__ void mma_tf32(float* d, const uint32_t* a, const uint32_t* b)
{
    asm volatile(
        "mma.sync.aligned.m16n8k8.row.col.f32.tf32.tf32.f32 "
        "{%0,%1,%2,%3}, {%4,%5,%6,%7}, {%8,%9}, {%0,%1,%2,%3};\n"
        : "+f"(d[0]), "+f"(d[1]), "+f"(d[2]), "+f"(d[3])
        : "r"(a[0]), "r"(a[1]), "r"(a[2]), "r"(a[3]), "r"(b[0]), "r"(b[1]));
}

__device__ __forceinline__ void cp16(uint32_t smem_addr, const void* gptr)
{
    asm volatile("cp.async.cg.shared.global [%0], [%1], 16;\n"
                 :: "r"(smem_addr), "l"(gptr));
}

// Split a float4 into 4 (hi,lo) float2 pairs, two 16B stores (flash K/V/P path).
__device__ __forceinline__ void st_split4(float2* dst, float4 v)
{
    uint32_t h0, l0, h1, l1, h2, l2, h3, l3;
    split_tf32(v.x, h0, l0); split_tf32(v.y, h1, l1);
    split_tf32(v.z, h2, l2); split_tf32(v.w, h3, l3);
    *(float4*)dst       = make_float4(__uint_as_float(h0), __uint_as_float(l0),
                                      __uint_as_float(h1), __uint_as_float(l1));
    *(float4*)(dst + 2) = make_float4(__uint_as_float(h2), __uint_as_float(l2),
                                      __uint_as_float(h3), __uint_as_float(l3));
}

// ---------------------------------------------------------------------------
// bf16x3 helpers (GEMM path).
// pack: v=(x0,x1) consecutive-k pair -> hi = {bf16(x1)|bf16(x0)},
//       lo = bf16x2 of residuals. Missing lo*lo term ~2^-18 per product.
// ---------------------------------------------------------------------------
__device__ __forceinline__ void pack_bf16x3(float x0, float x1,
                                            uint32_t& hi, uint32_t& lo)
{
    uint32_t h;
    asm("cvt.rn.bf16x2.f32 %0, %1, %2;" : "=r"(h) : "f"(x1), "f"(x0));
    float h0 = __uint_as_float(h << 16);         // low half = x0's bf16
    float h1 = __uint_as_float(h & 0xffff0000u); // high half = x1's bf16
    float r0 = x0 - h0;
    float r1 = x1 - h1;
    asm("cvt.rn.bf16x2.f32 %0, %1, %2;" : "=r"(lo) : "f"(r1), "f"(r0));
    hi = h;
}

__device__ __forceinline__ void mma_bf16(float* d, const uint32_t* a, const uint32_t* b)
{
    asm volatile(
        "mma.sync.aligned.m16n8k16.row.col.f32.bf16.bf16.f32 "
        "{%0,%1,%2,%3}, {%4,%5,%6,%7}, {%8,%9}, {%0,%1,%2,%3};\n"
        : "+f"(d[0]), "+f"(d[1]), "+f"(d[2]), "+f"(d[3])
        : "r"(a[0]), "r"(a[1]), "r"(a[2]), "r"(a[3]), "r"(b[0]), "r"(b[1]));
}

// ---------------------------------------------------------------------------
// bf16x3 tensor-core GEMM. Same structure as R13 (cp.async double-buffered
// raw-f32 smem, split-in-registers), but m16n8k16 bf16 MMAs: half the MMA
// count per K-slab at the same tensor-issue rate.
// Bank-checked pitches for the new access patterns:
//   APITCH=40: A float2 frag loads word=(4g+tg) mod 16 distinct/phase.
//   BPITCH=140: B scalar frag rows 2tg/2tg+1/+8: banks {0,24,16,8}+g and
//   +12-shifted — all 32 distinct. cp.async stores stay 16B-aligned.
// ---------------------------------------------------------------------------
#define BK      32
#define APITCH  40
#define BPITCH  140
#define A_SM    (128 * APITCH)        // 5120 floats
#define B_SM    (BK * BPITCH)         // 4480 floats
#define BUF_SM  (A_SM + B_SM)         // 9600 floats
#define GEMM_SMEM (2 * BUF_SM * 4)    // 76800 bytes (x2 CTAs = 153.6KB)

__device__ __forceinline__ void gemm_core(
    const float* __restrict__ A, const float* __restrict__ B,
    const float* __restrict__ bias, float* __restrict__ C,
    int K, int lda, int ldb, long long btileStride, int ldc)
{
    extern __shared__ float sm[];
    const uint32_t sm_u = (uint32_t)__cvta_generic_to_shared(sm);

    const int tid  = threadIdx.x;
    const int lane = tid & 31;
    const int w    = tid >> 5;
    const int warpM = w >> 2;
    const int warpN = w & 3;
    const int g  = lane >> 2;
    const int tg = lane & 3;

    const int mtile = blockIdx.x, ntile = blockIdx.y;

    const float* Abase = A + (size_t)(mtile * 128) * lda;
    const float* Bbase = B + (size_t)ntile * btileStride;

    const int a_kq = tid & 7;
    const int a_m0 = tid >> 3;
    const int b_n4 = tid & 31;
    const int b_k0 = tid >> 5;

    float acc[16][4];
#pragma unroll
    for (int i = 0; i < 16; i++)
#pragma unroll
        for (int j = 0; j < 4; j++) acc[i][j] = 0.0f;

    const int nt_iters = K >> 5;

#define ISSUE_TILE(kt, bf)                                                        \
    {                                                                             \
        uint32_t abuf = sm_u + (uint32_t)((bf) * BUF_SM) * 4u;                    \
        uint32_t bbuf = abuf + (uint32_t)A_SM * 4u;                               \
        _Pragma("unroll")                                                         \
        for (int i = 0; i < 4; i++) {                                             \
            int m = a_m0 + 32 * i;                                                \
            cp16(abuf + (uint32_t)(m * APITCH + a_kq * 4) * 4u,                   \
                 Abase + (size_t)m * lda + (kt) * BK + a_kq * 4);                 \
        }                                                                         \
        _Pragma("unroll")                                                         \
        for (int i = 0; i < 4; i++) {                                             \
            int k = b_k0 + 8 * i;                                                 \
            cp16(bbuf + (uint32_t)(k * BPITCH + b_n4 * 4) * 4u,                   \
                 Bbase + (size_t)((kt) * BK + k) * ldb + b_n4 * 4);               \
        }                                                                         \
        asm volatile("cp.async.commit_group;\n" ::);                              \
    }

    ISSUE_TILE(0, 0);

    int buf = 0;
    for (int kt = 0; kt < nt_iters; kt++) {
        if (kt + 1 < nt_iters) {
            ISSUE_TILE(kt + 1, buf ^ 1);
            asm volatile("cp.async.wait_group 1;\n" ::);
        } else {
            asm volatile("cp.async.wait_group 0;\n" ::);
        }
        __syncthreads();

        const float* Asb = sm + buf * BUF_SM;
        const float* Bsb = Asb + A_SM;

        // Two k16 steps per BK=32 slab
#pragma unroll
        for (int ks = 0; ks < 2; ks++) {
            const int k0 = ks * 16;

            // B fragments for the warp's 4 n-tiles (4 scalar LDS + 2 packs each)
            uint32_t bhi[4][2], blo[4][2];
#pragma unroll
            for (int nt = 0; nt < 4; nt++) {
                int n = warpN * 32 + nt * 8 + g;
                float b00 = Bsb[(k0 + 2 * tg) * BPITCH + n];
                float b01 = Bsb[(k0 + 2 * tg + 1) * BPITCH + n];
                float b10 = Bsb[(k0 + 2 * tg + 8) * BPITCH + n];
                float b11 = Bsb[(k0 + 2 * tg + 9) * BPITCH + n];
                pack_bf16x3(b00, b01, bhi[nt][0], blo[nt][0]);
                pack_bf16x3(b10, b11, bhi[nt][1], blo[nt][1]);
            }

#pragma unroll
            for (int mt = 0; mt < 4; mt++) {
                int m = warpM * 64 + mt * 16 + g;
                float2 a0 = *(const float2*)&Asb[m * APITCH + k0 + 2 * tg];
                float2 a1 = *(const float2*)&Asb[(m + 8) * APITCH + k0 + 2 * tg];
                float2 a2 = *(const float2*)&Asb[m * APITCH + k0 + 8 + 2 * tg];
                float2 a3 = *(const float2*)&Asb[(m + 8) * APITCH + k0 + 8 + 2 * tg];
                uint32_t ahi[4], alo[4];
                pack_bf16x3(a0.x, a0.y, ahi[0], alo[0]);
                pack_bf16x3(a1.x, a1.y, ahi[1], alo[1]);
                pack_bf16x3(a2.x, a2.y, ahi[2], alo[2]);
                pack_bf16x3(a3.x, a3.y, ahi[3], alo[3]);
#pragma unroll
                for (int nt = 0; nt < 4; nt++) {
                    float* d = acc[mt * 4 + nt];
                    mma_bf16(d, ahi, bhi[nt]);
                    mma_bf16(d, ahi, blo[nt]);
                    mma_bf16(d, alo, bhi[nt]);
                }
            }
        }

        __syncthreads();
        buf ^= 1;
    }

    // Epilogue: bias add + store (same accumulator layout as m16n8k8)
#pragma unroll
    for (int mt = 0; mt < 4; mt++) {
#pragma unroll
        for (int nt = 0; nt < 4; nt++) {
            const float* d = acc[mt * 4 + nt];
            int r0 = mtile * 128 + warpM * 64 + mt * 16 + g;
            int c  = ntile * 128 + warpN * 32 + nt * 8 + 2 * tg;
            float bx = bias[c], by = bias[c + 1];
            float2 lo = make_float2(d[0] + bx, d[1] + by);
            float2 hi = make_float2(d[2] + bx, d[3] + by);
            *(float2*)&C[(size_t)r0 * ldc + c]       = lo;
            *(float2*)&C[(size_t)(r0 + 8) * ldc + c] = hi;
        }
    }
#undef ISSUE_TILE
}

// Fused QKV projections: grid.z selects which projection this CTA computes.
__global__ __launch_bounds__(256) void qkv_gemm(
    const float* __restrict__ xq, const float* __restrict__ xk,
    const float* __restrict__ xv,
    const float* __restrict__ WQ, const float* __restrict__ WK,
    const float* __restrict__ WV,
    const float* __restrict__ bQ, const float* __restrict__ bK,
    const float* __restrict__ bV,
    float* __restrict__ q, float* __restrict__ k, float* __restrict__ v)
{
    const float *A, *B, *bias;
    float* C;
    if (blockIdx.z == 0)      { A = xq; B = WQ; bias = bQ; C = q; }
    else if (blockIdx.z == 1) { A = xk; B = WK; bias = bK; C = k; }
    else                      { A = xv; B = WV; bias = bV; C = v; }
    gemm_core(A, B, bias, C, ND, ND, NDH, (long long)ND * NDH, FEAT);
}

__global__ __launch_bounds__(256) void out_gemm(
    const float* __restrict__ A, const float* __restrict__ B,
    const float* __restrict__ bias, float* __restrict__ C)
{
    gemm_core(A, B, bias, C, FEAT, FEAT, ND, 128LL, ND);
}

// ---------------------------------------------------------------------------
// Rotary (in-place on q and k). Unchanged.
// ---------------------------------------------------------------------------
__global__ void rotary_kernel(float* __restrict__ q, float* __restrict__ k)
{
    int p = blockIdx.x * blockDim.x + threadIdx.x;
    int e = p & 63;
    int h = (p >> 6) & 15;
    int s = (p >> 10) & 2047;
    int b = p >> 21;

    float freq = powf(10000.0f, (float)e * (1.0f / 64.0f));
    float ang  = (float)s / freq;
    float sn, cs;
    sincosf(ang, &sn, &cs);

    size_t base = ((size_t)(b * NS + s) * NH + h) * NDH + e;

    float x0 = q[base], x1 = q[base + 64];
    q[base]      = x0 * cs - x1 * sn;
    q[base + 64] = x1 * cs + x0 * sn;

    x0 = k[base]; x1 = k[base + 64];
    k[base]      = x0 * cs - x1 * sn;
    k[base + 64] = x1 * cs + x0 * sn;
}

// ---------------------------------------------------------------------------
// Flash attention, tensor cores, PRE-SPLIT K/V/P (3xTF32, causal).
// Br=128 rows/CTA, Bc=32 keys/tile, 256 threads = 8 warps x 16 rows.
// Unchanged from R13 (measured ~840-860us).
// ---------------------------------------------------------------------------
#define FBC   32
#define FQP   132                       // Q pitch, f32
#define FKP   132                       // K/V pitch, f2
#define FPP   36                        // P pitch, f2
#define FQ_F32 (128 * FQP)              // 16896 floats
#define FK_F2  (FBC * FKP)              // 4224 f2
#define FP_F2  (16 * FPP)               // per-warp P: 576 f2
#define FLASH2_SMEM (FQ_F32 * 4 + (2 * FK_F2 + 8 * FP_F2) * 8)  // 172032 B

__global__ __launch_bounds__(256, 1) void flash_ps_kernel(
    const float* __restrict__ gq, const float* __restrict__ gk,
    const float* __restrict__ gv, float* __restrict__ gz)
{
    extern __shared__ char smraw[];
    float*  Qs  = (float*)smraw;
    float2* Ks2 = (float2*)(smraw + FQ_F32 * 4);
    float2* Vs2 = Ks2 + FK_F2;
    float2* Pbase = Vs2 + FK_F2;

    const int tid  = threadIdx.x;
    const int lane = tid & 31;
    const int w    = tid >> 5;
    const int g    = lane >> 2;
    const int tg   = lane & 3;
    const int qt   = blockIdx.x;      // 128-row query tile
    const int h    = blockIdx.y;
    const int b    = blockIdx.z;

    float2* Pw2 = Pbase + w * FP_F2;  // this warp's P buffer

    const size_t hb = (size_t)b * ((size_t)NS * NH * NDH) + (size_t)h * NDH;
    const float* qb = gq + hb;
    const float* kb = gk + hb;
    const float* vb = gv + hb;
    float* zb = gz + hb;

    const float scale = 0.08838834764831845f;   // 1/sqrt(128)
    const int ldrow = NH * NDH;                 // 2048

    // Load + pre-scale Q tile: 128 x 128
#pragma unroll
    for (int i = 0; i < 16; i++) {
        int idx = tid + 256 * i;
        int r = idx >> 5, c4 = idx & 31;
        float4 qv = *(const float4*)(qb + (size_t)(qt * 128 + r) * ldrow + c4 * 4);
        qv.x *= scale; qv.y *= scale; qv.z *= scale; qv.w *= scale;
        *(float4*)&Qs[r * FQP + c4 * 4] = qv;
    }

    float O[16][4];
#pragma unroll
    for (int i = 0; i < 16; i++)
#pragma unroll
        for (int j2 = 0; j2 < 4; j2++) O[i][j2] = 0.0f;
    float m0 = -INFINITY, m1 = -INFINITY, l0 = 0.0f, l1 = 0.0f;

    const int r0g = qt * 128 + w * 16 + g;
    const int r1g = r0g + 8;
    const int warp_rhi = qt * 128 + w * 16 + 15;
    const int jmax = 4 * qt + 3;

    for (int j = 0; j <= jmax; j++) {
        __syncthreads();
        // Load + split K,V tiles: 32 keys x 128 dims = 1024 float4 each
#pragma unroll
        for (int i = 0; i < 4; i++) {
            int idx = tid + 256 * i;
            int r = idx >> 5, c4 = idx & 31;
            size_t gofs = (size_t)(j * FBC + r) * ldrow + c4 * 4;
            st_split4(&Ks2[r * FKP + c4 * 4], *(const float4*)(kb + gofs));
            st_split4(&Vs2[r * FKP + c4 * 4], *(const float4*)(vb + gofs));
        }
        __syncthreads();

        if (j * FBC > warp_rhi) continue;   // warp-uniform: fully masked tile

        // ---- S = Q K^T : sacc[4 nt][4], keys j*32..j*32+31 ----
        float sacc[4][4];
#pragma unroll
        for (int nt = 0; nt < 4; nt++)
#pragma unroll
            for (int v = 0; v < 4; v++) sacc[nt][v] = 0.0f;

#pragma unroll
        for (int ks = 0; ks < 16; ks++) {
            const int k0 = ks * 8;
            const int m = w * 16 + g;
            float a0 = Qs[m * FQP + k0 + tg];
            float a1 = Qs[(m + 8) * FQP + k0 + tg];
            float a2 = Qs[m * FQP + k0 + tg + 4];
            float a3 = Qs[(m + 8) * FQP + k0 + tg + 4];
            uint32_t ahi[4], alo[4];
            split_tf32(a0, ahi[0], alo[0]);
            split_tf32(a1, ahi[1], alo[1]);
            split_tf32(a2, ahi[2], alo[2]);
            split_tf32(a3, ahi[3], alo[3]);
#pragma unroll
            for (int nt = 0; nt < 4; nt++) {
                int n = nt * 8 + g;            // key within tile
                float2 f0 = Ks2[n * FKP + k0 + tg];
                float2 f1 = Ks2[n * FKP + k0 + tg + 4];
                uint32_t bhi[2] = {__float_as_uint(f0.x), __float_as_uint(f1.x)};
                uint32_t blo[2] = {__float_as_uint(f0.y), __float_as_uint(f1.y)};
                mma_tf32(sacc[nt], ahi, bhi);
                mma_tf32(sacc[nt], ahi, blo);
                mma_tf32(sacc[nt], alo, bhi);
            }
        }

        // ---- causal mask on diagonal tiles ----
        if (j * FBC + FBC - 1 > r0g) {
#pragma unroll
            for (int nt = 0; nt < 4; nt++) {
                int c = j * FBC + nt * 8 + 2 * tg;
                if (c > r0g)     sacc[nt][0] = -1e30f;
                if (c + 1 > r0g) sacc[nt][1] = -1e30f;
                if (c > r1g)     sacc[nt][2] = -1e30f;
                if (c + 1 > r1g) sacc[nt][3] = -1e30f;
            }
        }

        // ---- online softmax in accumulator layout ----
        float rmax0 = -1e30f, rmax1 = -1e30f;
#pragma unroll
        for (int nt = 0; nt < 4; nt++) {
            rmax0 = fmaxf(rmax0, fmaxf(sacc[nt][0], sacc[nt][1]));
            rmax1 = fmaxf(rmax1, fmaxf(sacc[nt][2], sacc[nt][3]));
        }
        rmax0 = fmaxf(rmax0, __shfl_xor_sync(0xffffffffu, rmax0, 1));
        rmax0 = fmaxf(rmax0, __shfl_xor_sync(0xffffffffu, rmax0, 2));
        rmax1 = fmaxf(rmax1, __shfl_xor_sync(0xffffffffu, rmax1, 1));
        rmax1 = fmaxf(rmax1, __shfl_xor_sync(0xffffffffu, rmax1, 2));

        float mn0 = fmaxf(m0, rmax0), mn1 = fmaxf(m1, rmax1);
        float alpha0 = __expf(m0 - mn0), alpha1 = __expf(m1 - mn1);

        float ps0 = 0.0f, ps1 = 0.0f;
#pragma unroll
        for (int nt = 0; nt < 4; nt++) {
            float p0 = __expf(sacc[nt][0] - mn0);
            float p1 = __expf(sacc[nt][1] - mn0);
            float p2 = __expf(sacc[nt][2] - mn1);
            float p3 = __expf(sacc[nt][3] - mn1);
            ps0 += p0 + p1;
            ps1 += p2 + p3;
            uint32_t h0, l0u, h1, l1u;
            split_tf32(p0, h0, l0u); split_tf32(p1, h1, l1u);
            *(float4*)&Pw2[g * FPP + nt * 8 + 2 * tg] =
                make_float4(__uint_as_float(h0), __uint_as_float(l0u),
                            __uint_as_float(h1), __uint_as_float(l1u));
            split_tf32(p2, h0, l0u); split_tf32(p3, h1, l1u);
            *(float4*)&Pw2[(g + 8) * FPP + nt * 8 + 2 * tg] =
                make_float4(__uint_as_float(h0), __uint_as_float(l0u),
                            __uint_as_float(h1), __uint_as_float(l1u));
        }
        ps0 += __shfl_xor_sync(0xffffffffu, ps0, 1);
        ps0 += __shfl_xor_sync(0xffffffffu, ps0, 2);
        ps1 += __shfl_xor_sync(0xffffffffu, ps1, 1);
        ps1 += __shfl_xor_sync(0xffffffffu, ps1, 2);

        l0 = l0 * alpha0 + ps0;  m0 = mn0;
        l1 = l1 * alpha1 + ps1;  m1 = mn1;

#pragma unroll
        for (int nt = 0; nt < 16; nt++) {
            O[nt][0] *= alpha0; O[nt][1] *= alpha0;
            O[nt][2] *= alpha1; O[nt][3] *= alpha1;
        }
        __syncwarp();   // P visible to whole warp

        // ---- O += P V ----
#pragma unroll
        for (int ks = 0; ks < 4; ks++) {
            const int k0 = ks * 8;
            float2 f;
            uint32_t ahi[4], alo[4];
            f = Pw2[g * FPP + k0 + tg];
            ahi[0] = __float_as_uint(f.x); alo[0] = __float_as_uint(f.y);
            f = Pw2[(g + 8) * FPP + k0 + tg];
            ahi[1] = __float_as_uint(f.x); alo[1] = __float_as_uint(f.y);
            f = Pw2[g * FPP + k0 + tg + 4];
            ahi[2] = __float_as_uint(f.x); alo[2] = __float_as_uint(f.y);
            f = Pw2[(g + 8) * FPP + k0 + tg + 4];
            ahi[3] = __float_as_uint(f.x); alo[3] = __float_as_uint(f.y);
#pragma unroll
            for (int nt = 0; nt < 16; nt++) {
                int n = nt * 8 + g;            // dim
                float2 f0 = Vs2[(k0 + tg) * FKP + n];
                float2 f1 = Vs2[(k0 + tg + 4) * FKP + n];
                uint32_t bhi[2] = {__float_as_uint(f0.x), __float_as_uint(f1.x)};
                uint32_t blo[2] = {__float_as_uint(f0.y), __float_as_uint(f1.y)};
                mma_tf32(O[nt], ahi, bhi);
                mma_tf32(O[nt], ahi, blo);
                mma_tf32(O[nt], alo, bhi);
            }
        }
        __syncwarp();   // P consumed before next tile overwrites it
    }

    // ---- epilogue: normalize and store ----
    float inv0 = 1.0f / l0, inv1 = 1.0f / l1;
#pragma unroll
    for (int nt = 0; nt < 16; nt++) {
        int c = nt * 8 + 2 * tg;
        *(float2*)&zb[(size_t)r0g * ldrow + c] =
            make_float2(O[nt][0] * inv0, O[nt][1] * inv0);
        *(float2*)&zb[(size_t)r1g * ldrow + c] =
            make_float2(O[nt][2] * inv1, O[nt][3] * inv1);
    }
}

// ---------------------------------------------------------------------------
// Launcher
// ---------------------------------------------------------------------------
extern "C" void kernel_launch(void* const* d_in, const int* in_sizes, int n_in,
                              void* d_out, int out_size)
{
    const float* xq = (const float*)d_in[0];
    const float* xk = (const float*)d_in[1];
    const float* xv = (const float*)d_in[2];
    const float* WQ = (const float*)d_in[3];
    const float* WK = (const float*)d_in[4];
    const float* WV = (const float*)d_in[5];
    const float* WO = (const float*)d_in[6];
    const float* bQ = (const float*)d_in[7];
    const float* bK = (const float*)d_in[8];
    const float* bV = (const float*)d_in[9];
    const float* bO = (const float*)d_in[10];
    float* out = (float*)d_out;

    float *qp, *kp, *vp, *zp;
    cudaGetSymbolAddress((void**)&qp, g_q);
    cudaGetSymbolAddress((void**)&kp, g_k);
    cudaGetSymbolAddress((void**)&vp, g_v);
    cudaGetSymbolAddress((void**)&zp, g_z);

    cudaFuncSetAttribute(qkv_gemm,
                         cudaFuncAttributeMaxDynamicSharedMemorySize, GEMM_SMEM);
    cudaFuncSetAttribute(out_gemm,
                         cudaFuncAttributeMaxDynamicSharedMemorySize, GEMM_SMEM);
    cudaFuncSetAttribute(flash_ps_kernel,
                         cudaFuncAttributeMaxDynamicSharedMemorySize, FLASH2_SMEM);

    // Fused QKV projections: 32 x 16 x 3 CTAs in one launch
    dim3 gqkv(MROWS / 128, FEAT / 128, 3);
    qkv_gemm<<<gqkv, 256, GEMM_SMEM>>>(xq, xk, xv, WQ, WK, WV,
                                       bQ, bK, bV, qp, kp, vp);

    // Rotary on q and k
    rotary_kernel<<<16384, 256>>>(qp, kp);

    // Flash attention (tensor cores, pre-split operands)
    flash_ps_kernel<<<dim3(NS / 128, NH, NB), 256, FLASH2_SMEM>>>(qp, kp, vp, zp);

    // Output projection
    dim3 gout(MROWS / 128, FEAT / 128);
    out_gemm<<<gout, 256, GEMM_SMEM>>>(zp, WO, bO, out);
}

// round 16
// speedup vs baseline: 1.6621x; 1.6621x over previous
#include <cuda_runtime.h>
#include <math.h>
#include <stdint.h>

// Problem constants
#define NB   2
#define NS   2048
#define ND   2048
#define NH   16
#define NDH  128
#define MROWS (NB*NS)        // 4096 flattened (b,s) rows
#define FEAT  (NH*NDH)       // 2048 flattened (h,e) features

// Scratch buffers (allocation-free rule: __device__ globals)
#define QKV_ELEMS 8388608ull  // 4096 * 2048
__device__ float g_q[QKV_ELEMS];
__device__ float g_k[QKV_ELEMS];
__device__ float g_v[QKV_ELEMS];
__device__ float g_z[QKV_ELEMS];

// ---------------------------------------------------------------------------
// tf32 helpers (flash path, unchanged from R13)
// ---------------------------------------------------------------------------
__device__ __forceinline__ void split_tf32(float x, uint32_t& hi, uint32_t& lo)
{
    uint32_t h;
    asm("cvt.rna.tf32.f32 %0, %1;" : "=r"(h) : "f"(x));
    lo = __float_as_uint(x - __uint_as_float(h));
    hi = h;
}

__device__ __forceinline__ void mma_tf32(float* d, const uint32_t* a, const uint32_t* b)
{
    asm volatile(
        "mma.sync.aligned.m16n8k8.row.col.f32.tf32.tf32.f32 "
        "{%0,%1,%2,%3}, {%4,%5,%6,%7}, {%8,%9}, {%0,%1,%2,%3};\n"
        : "+f"(d[0]), "+f"(d[1]), "+f"(d[2]), "+f"(d[3])
        : "r"(a[0]), "r"(a[1]), "r"(a[2]), "r"(a[3]), "r"(b[0]), "r"(b[1]));
}

__device__ __forceinline__ void cp16(uint32_t smem_addr, const void* gptr)
{
    asm volatile("cp.async.cg.shared.global [%0], [%1], 16;\n"
                 :: "r"(smem_addr), "l"(gptr));
}

// Split a float4 into 4 (hi,lo) float2 pairs, two 16B stores (flash K/V/P path).
__device__ __forceinline__ void st_split4(float2* dst, float4 v)
{
    uint32_t h0, l0, h1, l1, h2, l2, h3, l3;
    split_tf32(v.x, h0, l0); split_tf32(v.y, h1, l1);
    split_tf32(v.z, h2, l2); split_tf32(v.w, h3, l3);
    *(float4*)dst       = make_float4(__uint_as_float(h0), __uint_as_float(l0),
                                      __uint_as_float(h1), __uint_as_float(l1));
    *(float4*)(dst + 2) = make_float4(__uint_as_float(h2), __uint_as_float(l2),
                                      __uint_as_float(h3), __uint_as_float(l3));
}

// ---------------------------------------------------------------------------
// bf16x3 helpers (GEMM path).
// pack: v=(x0,x1) consecutive-k pair -> hi = {bf16(x1)|bf16(x0)},
//       lo = bf16x2 of residuals. Missing lo*lo term ~2^-18 per product.
// ---------------------------------------------------------------------------
__device__ __forceinline__ void pack_bf16x3(float x0, float x1,
                                            uint32_t& hi, uint32_t& lo)
{
    uint32_t h;
    asm("cvt.rn.bf16x2.f32 %0, %1, %2;" : "=r"(h) : "f"(x1), "f"(x0));
    float h0 = __uint_as_float(h << 16);         // low half = x0's bf16
    float h1 = __uint_as_float(h & 0xffff0000u); // high half = x1's bf16
    float r0 = x0 - h0;
    float r1 = x1 - h1;
    asm("cvt.rn.bf16x2.f32 %0, %1, %2;" : "=r"(lo) : "f"(r1), "f"(r0));
    hi = h;
}

__device__ __forceinline__ void mma_bf16(float* d, const uint32_t* a, const uint32_t* b)
{
    asm volatile(
        "mma.sync.aligned.m16n8k16.row.col.f32.bf16.bf16.f32 "
        "{%0,%1,%2,%3}, {%4,%5,%6,%7}, {%8,%9}, {%0,%1,%2,%3};\n"
        : "+f"(d[0]), "+f"(d[1]), "+f"(d[2]), "+f"(d[3])
        : "r"(a[0]), "r"(a[1]), "r"(a[2]), "r"(a[3]), "r"(b[0]), "r"(b[1]));
}

// ---------------------------------------------------------------------------
// bf16x3 tensor-core GEMM. R15: __launch_bounds__(256, 2) added — R14's
// 133 regs broke 2-CTA residency (occ 12.5%), confounding the bf16 test.
// ---------------------------------------------------------------------------
#define BK      32
#define APITCH  40
#define BPITCH  140
#define A_SM    (128 * APITCH)        // 5120 floats
#define B_SM    (BK * BPITCH)         // 4480 floats
#define BUF_SM  (A_SM + B_SM)         // 9600 floats
#define GEMM_SMEM (2 * BUF_SM * 4)    // 76800 bytes (x2 CTAs = 153.6KB)

__device__ __forceinline__ void gemm_core(
    const float* __restrict__ A, const float* __restrict__ B,
    const float* __restrict__ bias, float* __restrict__ C,
    int K, int lda, int ldb, long long btileStride, int ldc)
{
    extern __shared__ float sm[];
    const uint32_t sm_u = (uint32_t)__cvta_generic_to_shared(sm);

    const int tid  = threadIdx.x;
    const int lane = tid & 31;
    const int w    = tid >> 5;
    const int warpM = w >> 2;
    const int warpN = w & 3;
    const int g  = lane >> 2;
    const int tg = lane & 3;

    const int mtile = blockIdx.x, ntile = blockIdx.y;

    const float* Abase = A + (size_t)(mtile * 128) * lda;
    const float* Bbase = B + (size_t)ntile * btileStride;

    const int a_kq = tid & 7;
    const int a_m0 = tid >> 3;
    const int b_n4 = tid & 31;
    const int b_k0 = tid >> 5;

    float acc[16][4];
#pragma unroll
    for (int i = 0; i < 16; i++)
#pragma unroll
        for (int j = 0; j < 4; j++) acc[i][j] = 0.0f;

    const int nt_iters = K >> 5;

#define ISSUE_TILE(kt, bf)                                                        \
    {                                                                             \
        uint32_t abuf = sm_u + (uint32_t)((bf) * BUF_SM) * 4u;                    \
        uint32_t bbuf = abuf + (uint32_t)A_SM * 4u;                               \
        _Pragma("unroll")                                                         \
        for (int i = 0; i < 4; i++) {                                             \
            int m = a_m0 + 32 * i;                                                \
            cp16(abuf + (uint32_t)(m * APITCH + a_kq * 4) * 4u,                   \
                 Abase + (size_t)m * lda + (kt) * BK + a_kq * 4);                 \
        }                                                                         \
        _Pragma("unroll")                                                         \
        for (int i = 0; i < 4; i++) {                                             \
            int k = b_k0 + 8 * i;                                                 \
            cp16(bbuf + (uint32_t)(k * BPITCH + b_n4 * 4) * 4u,                   \
                 Bbase + (size_t)((kt) * BK + k) * ldb + b_n4 * 4);               \
        }                                                                         \
        asm volatile("cp.async.commit_group;\n" ::);                              \
    }

    ISSUE_TILE(0, 0);

    int buf = 0;
    for (int kt = 0; kt < nt_iters; kt++) {
        if (kt + 1 < nt_iters) {
            ISSUE_TILE(kt + 1, buf ^ 1);
            asm volatile("cp.async.wait_group 1;\n" ::);
        } else {
            asm volatile("cp.async.wait_group 0;\n" ::);
        }
        __syncthreads();

        const float* Asb = sm + buf * BUF_SM;
        const float* Bsb = Asb + A_SM;

        // Two k16 steps per BK=32 slab
#pragma unroll
        for (int ks = 0; ks < 2; ks++) {
            const int k0 = ks * 16;

            // B fragments for the warp's 4 n-tiles (4 scalar LDS + 2 packs each)
            uint32_t bhi[4][2], blo[4][2];
#pragma unroll
            for (int nt = 0; nt < 4; nt++) {
                int n = warpN * 32 + nt * 8 + g;
                float b00 = Bsb[(k0 + 2 * tg) * BPITCH + n];
                float b01 = Bsb[(k0 + 2 * tg + 1) * BPITCH + n];
                float b10 = Bsb[(k0 + 2 * tg + 8) * BPITCH + n];
                float b11 = Bsb[(k0 + 2 * tg + 9) * BPITCH + n];
                pack_bf16x3(b00, b01, bhi[nt][0], blo[nt][0]);
                pack_bf16x3(b10, b11, bhi[nt][1], blo[nt][1]);
            }

#pragma unroll
            for (int mt = 0; mt < 4; mt++) {
                int m = warpM * 64 + mt * 16 + g;
                float2 a0 = *(const float2*)&Asb[m * APITCH + k0 + 2 * tg];
                float2 a1 = *(const float2*)&Asb[(m + 8) * APITCH + k0 + 2 * tg];
                float2 a2 = *(const float2*)&Asb[m * APITCH + k0 + 8 + 2 * tg];
                float2 a3 = *(const float2*)&Asb[(m + 8) * APITCH + k0 + 8 + 2 * tg];
                uint32_t ahi[4], alo[4];
                pack_bf16x3(a0.x, a0.y, ahi[0], alo[0]);
                pack_bf16x3(a1.x, a1.y, ahi[1], alo[1]);
                pack_bf16x3(a2.x, a2.y, ahi[2], alo[2]);
                pack_bf16x3(a3.x, a3.y, ahi[3], alo[3]);
#pragma unroll
                for (int nt = 0; nt < 4; nt++) {
                    float* d = acc[mt * 4 + nt];
                    mma_bf16(d, ahi, bhi[nt]);
                    mma_bf16(d, ahi, blo[nt]);
                    mma_bf16(d, alo, bhi[nt]);
                }
            }
        }

        __syncthreads();
        buf ^= 1;
    }

    // Epilogue: bias add + store (same accumulator layout as m16n8k8)
#pragma unroll
    for (int mt = 0; mt < 4; mt++) {
#pragma unroll
        for (int nt = 0; nt < 4; nt++) {
            const float* d = acc[mt * 4 + nt];
            int r0 = mtile * 128 + warpM * 64 + mt * 16 + g;
            int c  = ntile * 128 + warpN * 32 + nt * 8 + 2 * tg;
            float bx = bias[c], by = bias[c + 1];
            float2 lo = make_float2(d[0] + bx, d[1] + by);
            float2 hi = make_float2(d[2] + bx, d[3] + by);
            *(float2*)&C[(size_t)r0 * ldc + c]       = lo;
            *(float2*)&C[(size_t)(r0 + 8) * ldc + c] = hi;
        }
    }
#undef ISSUE_TILE
}

// Fused QKV projections: grid.z selects which projection this CTA computes.
__global__ __launch_bounds__(256, 2) void qkv_gemm(
    const float* __restrict__ xq, const float* __restrict__ xk,
    const float* __restrict__ xv,
    const float* __restrict__ WQ, const float* __restrict__ WK,
    const float* __restrict__ WV,
    const float* __restrict__ bQ, const float* __restrict__ bK,
    const float* __restrict__ bV,
    float* __restrict__ q, float* __restrict__ k, float* __restrict__ v)
{
    const float *A, *B, *bias;
    float* C;
    if (blockIdx.z == 0)      { A = xq; B = WQ; bias = bQ; C = q; }
    else if (blockIdx.z == 1) { A = xk; B = WK; bias = bK; C = k; }
    else                      { A = xv; B = WV; bias = bV; C = v; }
    gemm_core(A, B, bias, C, ND, ND, NDH, (long long)ND * NDH, FEAT);
}

__global__ __launch_bounds__(256, 2) void out_gemm(
    const float* __restrict__ A, const float* __restrict__ B,
    const float* __restrict__ bias, float* __restrict__ C)
{
    gemm_core(A, B, bias, C, FEAT, FEAT, ND, 128LL, ND);
}

// ---------------------------------------------------------------------------
// Rotary (in-place on q and k). Unchanged.
// ---------------------------------------------------------------------------
__global__ void rotary_kernel(float* __restrict__ q, float* __restrict__ k)
{
    int p = blockIdx.x * blockDim.x + threadIdx.x;
    int e = p & 63;
    int h = (p >> 6) & 15;
    int s = (p >> 10) & 2047;
    int b = p >> 21;

    float freq = powf(10000.0f, (float)e * (1.0f / 64.0f));
    float ang  = (float)s / freq;
    float sn, cs;
    sincosf(ang, &sn, &cs);

    size_t base = ((size_t)(b * NS + s) * NH + h) * NDH + e;

    float x0 = q[base], x1 = q[base + 64];
    q[base]      = x0 * cs - x1 * sn;
    q[base + 64] = x1 * cs + x0 * sn;

    x0 = k[base]; x1 = k[base + 64];
    k[base]      = x0 * cs - x1 * sn;
    k[base + 64] = x1 * cs + x0 * sn;
}

// ---------------------------------------------------------------------------
// Flash attention, tensor cores, PRE-SPLIT K/V/P (3xTF32, causal).
// Br=128 rows/CTA, Bc=32 keys/tile, 256 threads = 8 warps x 16 rows.
// Unchanged from R13 (measured ~840-860us).
// ---------------------------------------------------------------------------
#define FBC   32
#define FQP   132                       // Q pitch, f32
#define FKP   132                       // K/V pitch, f2
#define FPP   36                        // P pitch, f2
#define FQ_F32 (128 * FQP)              // 16896 floats
#define FK_F2  (FBC * FKP)              // 4224 f2
#define FP_F2  (16 * FPP)               // per-warp P: 576 f2
#define FLASH2_SMEM (FQ_F32 * 4 + (2 * FK_F2 + 8 * FP_F2) * 8)  // 172032 B

__global__ __launch_bounds__(256, 1) void flash_ps_kernel(
    const float* __restrict__ gq, const float* __restrict__ gk,
    const float* __restrict__ gv, float* __restrict__ gz)
{
    extern __shared__ char smraw[];
    float*  Qs  = (float*)smraw;
    float2* Ks2 = (float2*)(smraw + FQ_F32 * 4);
    float2* Vs2 = Ks2 + FK_F2;
    float2* Pbase = Vs2 + FK_F2;

    const int tid  = threadIdx.x;
    const int lane = tid & 31;
    const int w    = tid >> 5;
    const int g    = lane >> 2;
    const int tg   = lane & 3;
    const int qt   = blockIdx.x;      // 128-row query tile
    const int h    = blockIdx.y;
    const int b    = blockIdx.z;

    float2* Pw2 = Pbase + w * FP_F2;  // this warp's P buffer

    const size_t hb = (size_t)b * ((size_t)NS * NH * NDH) + (size_t)h * NDH;
    const float* qb = gq + hb;
    const float* kb = gk + hb;
    const float* vb = gv + hb;
    float* zb = gz + hb;

    const float scale = 0.08838834764831845f;   // 1/sqrt(128)
    const int ldrow = NH * NDH;                 // 2048

    // Load + pre-scale Q tile: 128 x 128
#pragma unroll
    for (int i = 0; i < 16; i++) {
        int idx = tid + 256 * i;
        int r = idx >> 5, c4 = idx & 31;
        float4 qv = *(const float4*)(qb + (size_t)(qt * 128 + r) * ldrow + c4 * 4);
        qv.x *= scale; qv.y *= scale; qv.z *= scale; qv.w *= scale;
        *(float4*)&Qs[r * FQP + c4 * 4] = qv;
    }

    float O[16][4];
#pragma unroll
    for (int i = 0; i < 16; i++)
#pragma unroll
        for (int j2 = 0; j2 < 4; j2++) O[i][j2] = 0.0f;
    float m0 = -INFINITY, m1 = -INFINITY, l0 = 0.0f, l1 = 0.0f;

    const int r0g = qt * 128 + w * 16 + g;
    const int r1g = r0g + 8;
    const int warp_rhi = qt * 128 + w * 16 + 15;
    const int jmax = 4 * qt + 3;

    for (int j = 0; j <= jmax; j++) {
        __syncthreads();
        // Load + split K,V tiles: 32 keys x 128 dims = 1024 float4 each
#pragma unroll
        for (int i = 0; i < 4; i++) {
            int idx = tid + 256 * i;
            int r = idx >> 5, c4 = idx & 31;
            size_t gofs = (size_t)(j * FBC + r) * ldrow + c4 * 4;
            st_split4(&Ks2[r * FKP + c4 * 4], *(const float4*)(kb + gofs));
            st_split4(&Vs2[r * FKP + c4 * 4], *(const float4*)(vb + gofs));
        }
        __syncthreads();

        if (j * FBC > warp_rhi) continue;   // warp-uniform: fully masked tile

        // ---- S = Q K^T : sacc[4 nt][4], keys j*32..j*32+31 ----
        float sacc[4][4];
#pragma unroll
        for (int nt = 0; nt < 4; nt++)
#pragma unroll
            for (int v = 0; v < 4; v++) sacc[nt][v] = 0.0f;

#pragma unroll
        for (int ks = 0; ks < 16; ks++) {
            const int k0 = ks * 8;
            const int m = w * 16 + g;
            float a0 = Qs[m * FQP + k0 + tg];
            float a1 = Qs[(m + 8) * FQP + k0 + tg];
            float a2 = Qs[m * FQP + k0 + tg + 4];
            float a3 = Qs[(m + 8) * FQP + k0 + tg + 4];
            uint32_t ahi[4], alo[4];
            split_tf32(a0, ahi[0], alo[0]);
            split_tf32(a1, ahi[1], alo[1]);
            split_tf32(a2, ahi[2], alo[2]);
            split_tf32(a3, ahi[3], alo[3]);
#pragma unroll
            for (int nt = 0; nt < 4; nt++) {
                int n = nt * 8 + g;            // key within tile
                float2 f0 = Ks2[n * FKP + k0 + tg];
                float2 f1 = Ks2[n * FKP + k0 + tg + 4];
                uint32_t bhi[2] = {__float_as_uint(f0.x), __float_as_uint(f1.x)};
                uint32_t blo[2] = {__float_as_uint(f0.y), __float_as_uint(f1.y)};
                mma_tf32(sacc[nt], ahi, bhi);
                mma_tf32(sacc[nt], ahi, blo);
                mma_tf32(sacc[nt], alo, bhi);
            }
        }

        // ---- causal mask on diagonal tiles ----
        if (j * FBC + FBC - 1 > r0g) {
#pragma unroll
            for (int nt = 0; nt < 4; nt++) {
                int c = j * FBC + nt * 8 + 2 * tg;
                if (c > r0g)     sacc[nt][0] = -1e30f;
                if (c + 1 > r0g) sacc[nt][1] = -1e30f;
                if (c > r1g)     sacc[nt][2] = -1e30f;
                if (c + 1 > r1g) sacc[nt][3] = -1e30f;
            }
        }

        // ---- online softmax in accumulator layout ----
        float rmax0 = -1e30f, rmax1 = -1e30f;
#pragma unroll
        for (int nt = 0; nt < 4; nt++) {
            rmax0 = fmaxf(rmax0, fmaxf(sacc[nt][0], sacc[nt][1]));
            rmax1 = fmaxf(rmax1, fmaxf(sacc[nt][2], sacc[nt][3]));
        }
        rmax0 = fmaxf(rmax0, __shfl_xor_sync(0xffffffffu, rmax0, 1));
        rmax0 = fmaxf(rmax0, __shfl_xor_sync(0xffffffffu, rmax0, 2));
        rmax1 = fmaxf(rmax1, __shfl_xor_sync(0xffffffffu, rmax1, 1));
        rmax1 = fmaxf(rmax1, __shfl_xor_sync(0xffffffffu, rmax1, 2));

        float mn0 = fmaxf(m0, rmax0), mn1 = fmaxf(m1, rmax1);
        float alpha0 = __expf(m0 - mn0), alpha1 = __expf(m1 - mn1);

        float ps0 = 0.0f, ps1 = 0.0f;
#pragma unroll
        for (int nt = 0; nt < 4; nt++) {
            float p0 = __expf(sacc[nt][0] - mn0);
            float p1 = __expf(sacc[nt][1] - mn0);
            float p2 = __expf(sacc[nt][2] - mn1);
            float p3 = __expf(sacc[nt][3] - mn1);
            ps0 += p0 + p1;
            ps1 += p2 + p3;
            uint32_t h0, l0u, h1, l1u;
            split_tf32(p0, h0, l0u); split_tf32(p1, h1, l1u);
            *(float4*)&Pw2[g * FPP + nt * 8 + 2 * tg] =
                make_float4(__uint_as_float(h0), __uint_as_float(l0u),
                            __uint_as_float(h1), __uint_as_float(l1u));
            split_tf32(p2, h0, l0u); split_tf32(p3, h1, l1u);
            *(float4*)&Pw2[(g + 8) * FPP + nt * 8 + 2 * tg] =
                make_float4(__uint_as_float(h0), __uint_as_float(l0u),
                            __uint_as_float(h1), __uint_as_float(l1u));
        }
        ps0 += __shfl_xor_sync(0xffffffffu, ps0, 1);
        ps0 += __shfl_xor_sync(0xffffffffu, ps0, 2);
        ps1 += __shfl_xor_sync(0xffffffffu, ps1, 1);
        ps1 += __shfl_xor_sync(0xffffffffu, ps1, 2);

        l0 = l0 * alpha0 + ps0;  m0 = mn0;
        l1 = l1 * alpha1 + ps1;  m1 = mn1;

#pragma unroll
        for (int nt = 0; nt < 16; nt++) {
            O[nt][0] *= alpha0; O[nt][1] *= alpha0;
            O[nt][2] *= alpha1; O[nt][3] *= alpha1;
        }
        __syncwarp();   // P visible to whole warp

        // ---- O += P V ----
#pragma unroll
        for (int ks = 0; ks < 4; ks++) {
            const int k0 = ks * 8;
            float2 f;
            uint32_t ahi[4], alo[4];
            f = Pw2[g * FPP + k0 + tg];
            ahi[0] = __float_as_uint(f.x); alo[0] = __float_as_uint(f.y);
            f = Pw2[(g + 8) * FPP + k0 + tg];
            ahi[1] = __float_as_uint(f.x); alo[1] = __float_as_uint(f.y);
            f = Pw2[g * FPP + k0 + tg + 4];
            ahi[2] = __float_as_uint(f.x); alo[2] = __float_as_uint(f.y);
            f = Pw2[(g + 8) * FPP + k0 + tg + 4];
            ahi[3] = __float_as_uint(f.x); alo[3] = __float_as_uint(f.y);
#pragma unroll
            for (int nt = 0; nt < 16; nt++) {
                int n = nt * 8 + g;            // dim
                float2 f0 = Vs2[(k0 + tg) * FKP + n];
                float2 f1 = Vs2[(k0 + tg + 4) * FKP + n];
                uint32_t bhi[2] = {__float_as_uint(f0.x), __float_as_uint(f1.x)};
                uint32_t blo[2] = {__float_as_uint(f0.y), __float_as_uint(f1.y)};
                mma_tf32(O[nt], ahi, bhi);
                mma_tf32(O[nt], ahi, blo);
                mma_tf32(O[nt], alo, bhi);
            }
        }
        __syncwarp();   // P consumed before next tile overwrites it
    }

    // ---- epilogue: normalize and store ----
    float inv0 = 1.0f / l0, inv1 = 1.0f / l1;
#pragma unroll
    for (int nt = 0; nt < 16; nt++) {
        int c = nt * 8 + 2 * tg;
        *(float2*)&zb[(size_t)r0g * ldrow + c] =
            make_float2(O[nt][0] * inv0, O[nt][1] * inv0);
        *(float2*)&zb[(size_t)r1g * ldrow + c] =
            make_float2(O[nt][2] * inv1, O[nt][3] * inv1);
    }
}

// ---------------------------------------------------------------------------
// Launcher
// ---------------------------------------------------------------------------
extern "C" void kernel_launch(void* const* d_in, const int* in_sizes, int n_in,
                              void* d_out, int out_size)
{
    const float* xq = (const float*)d_in[0];
    const float* xk = (const float*)d_in[1];
    const float* xv = (const float*)d_in[2];
    const float* WQ = (const float*)d_in[3];
    const float* WK = (const float*)d_in[4];
    const float* WV = (const float*)d_in[5];
    const float* WO = (const float*)d_in[6];
    const float* bQ = (const float*)d_in[7];
    const float* bK = (const float*)d_in[8];
    const float* bV = (const float*)d_in[9];
    const float* bO = (const float*)d_in[10];
    float* out = (float*)d_out;

    float *qp, *kp, *vp, *zp;
    cudaGetSymbolAddress((void**)&qp, g_q);
    cudaGetSymbolAddress((void**)&kp, g_k);
    cudaGetSymbolAddress((void**)&vp, g_v);
    cudaGetSymbolAddress((void**)&zp, g_z);

    cudaFuncSetAttribute(qkv_gemm,
                         cudaFuncAttributeMaxDynamicSharedMemorySize, GEMM_SMEM);
    cudaFuncSetAttribute(out_gemm,
                         cudaFuncAttributeMaxDynamicSharedMemorySize, GEMM_SMEM);
    cudaFuncSetAttribute(flash_ps_kernel,
                         cudaFuncAttributeMaxDynamicSharedMemorySize, FLASH2_SMEM);

    // Fused QKV projections: 32 x 16 x 3 CTAs in one launch
    dim3 gqkv(MROWS / 128, FEAT / 128, 3);
    qkv_gemm<<<gqkv, 256, GEMM_SMEM>>>(xq, xk, xv, WQ, WK, WV,
                                       bQ, bK, bV, qp, kp, vp);

    // Rotary on q and k
    rotary_kernel<<<16384, 256>>>(qp, kp);

    // Flash attention (tensor cores, pre-split operands)
    flash_ps_kernel<<<dim3(NS / 128, NH, NB), 256, FLASH2_SMEM>>>(qp, kp, vp, zp);

    // Output projection
    dim3 gout(MROWS / 128, FEAT / 128);
    out_gemm<<<gout, 256, GEMM_SMEM>>>(zp, WO, bO, out);
}

// round 17
// speedup vs baseline: 1.9968x; 1.2013x over previous
#include <cuda_runtime.h>
#include <math.h>
#include <stdint.h>

// Problem constants
#define NB   2
#define NS   2048
#define ND   2048
#define NH   16
#define NDH  128
#define MROWS (NB*NS)        // 4096 flattened (b,s) rows
#define FEAT  (NH*NDH)       // 2048 flattened (h,e) features

// Scratch buffers (allocation-free rule: __device__ globals)
#define QKV_ELEMS 8388608ull  // 4096 * 2048
__device__ float g_q[QKV_ELEMS];
__device__ float g_k[QKV_ELEMS];
__device__ float g_v[QKV_ELEMS];
__device__ float g_z[QKV_ELEMS];

// ---------------------------------------------------------------------------
// bf16x3 helpers (GEMM + flash).
// pack: (x0,x1) consecutive-k pair -> hi = {bf16(x1)|bf16(x0)},
//       lo = bf16x2 of residuals. Missing lo*lo term ~2^-18 per product.
// ---------------------------------------------------------------------------
__device__ __forceinline__ void pack_bf16x3(float x0, float x1,
                                            uint32_t& hi, uint32_t& lo)
{
    uint32_t h;
    asm("cvt.rn.bf16x2.f32 %0, %1, %2;" : "=r"(h) : "f"(x1), "f"(x0));
    float h0 = __uint_as_float(h << 16);         // low half = x0's bf16
    float h1 = __uint_as_float(h & 0xffff0000u); // high half = x1's bf16
    float r0 = x0 - h0;
    float r1 = x1 - h1;
    asm("cvt.rn.bf16x2.f32 %0, %1, %2;" : "=r"(lo) : "f"(r1), "f"(r0));
    hi = h;
}

__device__ __forceinline__ void mma_bf16(float* d, const uint32_t* a, const uint32_t* b)
{
    asm volatile(
        "mma.sync.aligned.m16n8k16.row.col.f32.bf16.bf16.f32 "
        "{%0,%1,%2,%3}, {%4,%5,%6,%7}, {%8,%9}, {%0,%1,%2,%3};\n"
        : "+f"(d[0]), "+f"(d[1]), "+f"(d[2]), "+f"(d[3])
        : "r"(a[0]), "r"(a[1]), "r"(a[2]), "r"(a[3]), "r"(b[0]), "r"(b[1]));
}

__device__ __forceinline__ void cp16(uint32_t smem_addr, const void* gptr)
{
    asm volatile("cp.async.cg.shared.global [%0], [%1], 16;\n"
                 :: "r"(smem_addr), "l"(gptr));
}

// ---------------------------------------------------------------------------
// bf16x3 tensor-core GEMM (unchanged from R15 winner: 344us/GEMM,
// __launch_bounds__(256,2) pins 2 CTAs/SM).
// ---------------------------------------------------------------------------
#define BK      32
#define APITCH  40
#define BPITCH  140
#define A_SM    (128 * APITCH)        // 5120 floats
#define B_SM    (BK * BPITCH)         // 4480 floats
#define BUF_SM  (A_SM + B_SM)         // 9600 floats
#define GEMM_SMEM (2 * BUF_SM * 4)    // 76800 bytes (x2 CTAs = 153.6KB)

__device__ __forceinline__ void gemm_core(
    const float* __restrict__ A, const float* __restrict__ B,
    const float* __restrict__ bias, float* __restrict__ C,
    int K, int lda, int ldb, long long btileStride, int ldc)
{
    extern __shared__ float sm[];
    const uint32_t sm_u = (uint32_t)__cvta_generic_to_shared(sm);

    const int tid  = threadIdx.x;
    const int lane = tid & 31;
    const int w    = tid >> 5;
    const int warpM = w >> 2;
    const int warpN = w & 3;
    const int g  = lane >> 2;
    const int tg = lane & 3;

    const int mtile = blockIdx.x, ntile = blockIdx.y;

    const float* Abase = A + (size_t)(mtile * 128) * lda;
    const float* Bbase = B + (size_t)ntile * btileStride;

    const int a_kq = tid & 7;
    const int a_m0 = tid >> 3;
    const int b_n4 = tid & 31;
    const int b_k0 = tid >> 5;

    float acc[16][4];
#pragma unroll
    for (int i = 0; i < 16; i++)
#pragma unroll
        for (int j = 0; j < 4; j++) acc[i][j] = 0.0f;

    const int nt_iters = K >> 5;

#define ISSUE_TILE(kt, bf)                                                        \
    {                                                                             \
        uint32_t abuf = sm_u + (uint32_t)((bf) * BUF_SM) * 4u;                    \
        uint32_t bbuf = abuf + (uint32_t)A_SM * 4u;                               \
        _Pragma("unroll")                                                         \
        for (int i = 0; i < 4; i++) {                                             \
            int m = a_m0 + 32 * i;                                                \
            cp16(abuf + (uint32_t)(m * APITCH + a_kq * 4) * 4u,                   \
                 Abase + (size_t)m * lda + (kt) * BK + a_kq * 4);                 \
        }                                                                         \
        _Pragma("unroll")                                                         \
        for (int i = 0; i < 4; i++) {                                             \
            int k = b_k0 + 8 * i;                                                 \
            cp16(bbuf + (uint32_t)(k * BPITCH + b_n4 * 4) * 4u,                   \
                 Bbase + (size_t)((kt) * BK + k) * ldb + b_n4 * 4);               \
        }                                                                         \
        asm volatile("cp.async.commit_group;\n" ::);                              \
    }

    ISSUE_TILE(0, 0);

    int buf = 0;
    for (int kt = 0; kt < nt_iters; kt++) {
        if (kt + 1 < nt_iters) {
            ISSUE_TILE(kt + 1, buf ^ 1);
            asm volatile("cp.async.wait_group 1;\n" ::);
        } else {
            asm volatile("cp.async.wait_group 0;\n" ::);
        }
        __syncthreads();

        const float* Asb = sm + buf * BUF_SM;
        const float* Bsb = Asb + A_SM;

#pragma unroll
        for (int ks = 0; ks < 2; ks++) {
            const int k0 = ks * 16;

            uint32_t bhi[4][2], blo[4][2];
#pragma unroll
            for (int nt = 0; nt < 4; nt++) {
                int n = warpN * 32 + nt * 8 + g;
                float b00 = Bsb[(k0 + 2 * tg) * BPITCH + n];
                float b01 = Bsb[(k0 + 2 * tg + 1) * BPITCH + n];
                float b10 = Bsb[(k0 + 2 * tg + 8) * BPITCH + n];
                float b11 = Bsb[(k0 + 2 * tg + 9) * BPITCH + n];
                pack_bf16x3(b00, b01, bhi[nt][0], blo[nt][0]);
                pack_bf16x3(b10, b11, bhi[nt][1], blo[nt][1]);
            }

#pragma unroll
            for (int mt = 0; mt < 4; mt++) {
                int m = warpM * 64 + mt * 16 + g;
                float2 a0 = *(const float2*)&Asb[m * APITCH + k0 + 2 * tg];
                float2 a1 = *(const float2*)&Asb[(m + 8) * APITCH + k0 + 2 * tg];
                float2 a2 = *(const float2*)&Asb[m * APITCH + k0 + 8 + 2 * tg];
                float2 a3 = *(const float2*)&Asb[(m + 8) * APITCH + k0 + 8 + 2 * tg];
                uint32_t ahi[4], alo[4];
                pack_bf16x3(a0.x, a0.y, ahi[0], alo[0]);
                pack_bf16x3(a1.x, a1.y, ahi[1], alo[1]);
                pack_bf16x3(a2.x, a2.y, ahi[2], alo[2]);
                pack_bf16x3(a3.x, a3.y, ahi[3], alo[3]);
#pragma unroll
                for (int nt = 0; nt < 4; nt++) {
                    float* d = acc[mt * 4 + nt];
                    mma_bf16(d, ahi, bhi[nt]);
                    mma_bf16(d, ahi, blo[nt]);
                    mma_bf16(d, alo, bhi[nt]);
                }
            }
        }

        __syncthreads();
        buf ^= 1;
    }

#pragma unroll
    for (int mt = 0; mt < 4; mt++) {
#pragma unroll
        for (int nt = 0; nt < 4; nt++) {
            const float* d = acc[mt * 4 + nt];
            int r0 = mtile * 128 + warpM * 64 + mt * 16 + g;
            int c  = ntile * 128 + warpN * 32 + nt * 8 + 2 * tg;
            float bx = bias[c], by = bias[c + 1];
            float2 lo = make_float2(d[0] + bx, d[1] + by);
            float2 hi = make_float2(d[2] + bx, d[3] + by);
            *(float2*)&C[(size_t)r0 * ldc + c]       = lo;
            *(float2*)&C[(size_t)(r0 + 8) * ldc + c] = hi;
        }
    }
#undef ISSUE_TILE
}

__global__ __launch_bounds__(256, 2) void qkv_gemm(
    const float* __restrict__ xq, const float* __restrict__ xk,
    const float* __restrict__ xv,
    const float* __restrict__ WQ, const float* __restrict__ WK,
    const float* __restrict__ WV,
    const float* __restrict__ bQ, const float* __restrict__ bK,
    const float* __restrict__ bV,
    float* __restrict__ q, float* __restrict__ k, float* __restrict__ v)
{
    const float *A, *B, *bias;
    float* C;
    if (blockIdx.z == 0)      { A = xq; B = WQ; bias = bQ; C = q; }
    else if (blockIdx.z == 1) { A = xk; B = WK; bias = bK; C = k; }
    else                      { A = xv; B = WV; bias = bV; C = v; }
    gemm_core(A, B, bias, C, ND, ND, NDH, (long long)ND * NDH, FEAT);
}

__global__ __launch_bounds__(256, 2) void out_gemm(
    const float* __restrict__ A, const float* __restrict__ B,
    const float* __restrict__ bias, float* __restrict__ C)
{
    gemm_core(A, B, bias, C, FEAT, FEAT, ND, 128LL, ND);
}

// ---------------------------------------------------------------------------
// Rotary (in-place on q and k). Unchanged.
// ---------------------------------------------------------------------------
__global__ void rotary_kernel(float* __restrict__ q, float* __restrict__ k)
{
    int p = blockIdx.x * blockDim.x + threadIdx.x;
    int e = p & 63;
    int h = (p >> 6) & 15;
    int s = (p >> 10) & 2047;
    int b = p >> 21;

    float freq = powf(10000.0f, (float)e * (1.0f / 64.0f));
    float ang  = (float)s / freq;
    float sn, cs;
    sincosf(ang, &sn, &cs);

    size_t base = ((size_t)(b * NS + s) * NH + h) * NDH + e;

    float x0 = q[base], x1 = q[base + 64];
    q[base]      = x0 * cs - x1 * sn;
    q[base + 64] = x1 * cs + x0 * sn;

    x0 = k[base]; x1 = k[base + 64];
    k[base]      = x0 * cs - x1 * sn;
    k[base + 64] = x1 * cs + x0 * sn;
}

// ---------------------------------------------------------------------------
// Flash attention v3: bf16x3 m16n8k16 everywhere, causal.
// Br=128 rows/CTA, Bc=32 keys/tile, 256 threads = 8 warps x 16 rows.
//  - Q raw f32 in smem (pitch 136; float2 a-loads phase-conflict-free).
//  - K pre-split at load: Ks2[key][dimpair] = float2(bf16x2 hi, bf16x2 lo),
//    pitch 68 (== 4 mod 16 -> 4g+tg distinct).
//  - V pre-split AND transposed at load: Vt2[dim][keypair] float2(hi,lo),
//    pitch 20 (== 4 mod 16). Key pairs packed in bf16x2 -> PV B-frags are
//    direct 8B loads.
//  - P stays in REGISTERS: QK accumulator layout (rows g/g+8, keys 2tg,2tg+1)
//    is exactly the m16n8k16 A-fragment layout, so exp() values pack straight
//    into bf16x2 A-operands. No P smem, no extra syncs.
// ---------------------------------------------------------------------------
#define FBC    32
#define FQP    136                       // Q pitch, f32
#define KP2    68                        // K pitch, float2 (64 dim-pairs + pad)
#define VP2    20                        // V^T pitch, float2 (16 keypairs + pad)
#define FQ_BYTES  (128 * FQP * 4)        // 69632
#define FK_BYTES  (FBC * KP2 * 8)        // 17408
#define FV_BYTES  (128 * VP2 * 8)        // 20480
#define FLASH3_SMEM (FQ_BYTES + FK_BYTES + FV_BYTES)   // 107520 B

__global__ __launch_bounds__(256, 1) void flash_bf16_kernel(
    const float* __restrict__ gq, const float* __restrict__ gk,
    const float* __restrict__ gv, float* __restrict__ gz)
{
    extern __shared__ char smraw[];
    float*  Qs  = (float*)smraw;
    float2* Ks2 = (float2*)(smraw + FQ_BYTES);
    float2* Vt2 = (float2*)(smraw + FQ_BYTES + FK_BYTES);

    const int tid  = threadIdx.x;
    const int lane = tid & 31;
    const int w    = tid >> 5;
    const int g    = lane >> 2;
    const int tg   = lane & 3;
    const int qt   = blockIdx.x;      // 128-row query tile
    const int h    = blockIdx.y;
    const int b    = blockIdx.z;

    const size_t hb = (size_t)b * ((size_t)NS * NH * NDH) + (size_t)h * NDH;
    const float* qb = gq + hb;
    const float* kb = gk + hb;
    const float* vb = gv + hb;
    float* zb = gz + hb;

    const float scale = 0.08838834764831845f;   // 1/sqrt(128)
    const int ldrow = NH * NDH;                 // 2048

    // Load + pre-scale Q tile: 128 x 128 (raw f32, pitch 136)
#pragma unroll
    for (int i = 0; i < 16; i++) {
        int idx = tid + 256 * i;
        int r = idx >> 5, c4 = idx & 31;
        float4 qv = *(const float4*)(qb + (size_t)(qt * 128 + r) * ldrow + c4 * 4);
        qv.x *= scale; qv.y *= scale; qv.z *= scale; qv.w *= scale;
        *(float4*)&Qs[r * FQP + c4 * 4] = qv;
    }

    float O[16][4];
#pragma unroll
    for (int i = 0; i < 16; i++)
#pragma unroll
        for (int j2 = 0; j2 < 4; j2++) O[i][j2] = 0.0f;
    float m0 = -INFINITY, m1 = -INFINITY, l0 = 0.0f, l1 = 0.0f;

    const int mrow = w * 16 + g;                // warp-local A row
    const int r0g = qt * 128 + mrow;            // global row 0
    const int r1g = r0g + 8;                    // global row 1
    const int warp_rhi = qt * 128 + w * 16 + 15;
    const int jmax = 4 * qt + 3;

    for (int j = 0; j <= jmax; j++) {
        __syncthreads();
        // ---- K tile: 32 keys x 128 dims, split to bf16x2 pairs ----
#pragma unroll
        for (int i = 0; i < 4; i++) {
            int idx = tid + 256 * i;
            int r = idx >> 5, c4 = idx & 31;
            float4 k4 = *(const float4*)(kb + (size_t)(j * FBC + r) * ldrow + c4 * 4);
            uint32_t h0, l0u, h1, l1u;
            pack_bf16x3(k4.x, k4.y, h0, l0u);
            pack_bf16x3(k4.z, k4.w, h1, l1u);
            *(float4*)&Ks2[r * KP2 + 2 * c4] =
                make_float4(__uint_as_float(h0), __uint_as_float(l0u),
                            __uint_as_float(h1), __uint_as_float(l1u));
        }
        // ---- V tile: transposed + key-pair packed ----
#pragma unroll
        for (int i = 0; i < 2; i++) {
            int task = tid + 256 * i;
            int c4 = task >> 4;          // dim quad 0..31
            int kp = task & 15;          // keypair 0..15
            const float* va = vb + (size_t)(j * FBC + 2 * kp) * ldrow + c4 * 4;
            float4 vA = *(const float4*)va;
            float4 vB = *(const float4*)(va + ldrow);
            uint32_t hh, ll;
            pack_bf16x3(vA.x, vB.x, hh, ll);
            Vt2[(4 * c4 + 0) * VP2 + kp] = make_float2(__uint_as_float(hh), __uint_as_float(ll));
            pack_bf16x3(vA.y, vB.y, hh, ll);
            Vt2[(4 * c4 + 1) * VP2 + kp] = make_float2(__uint_as_float(hh), __uint_as_float(ll));
            pack_bf16x3(vA.z, vB.z, hh, ll);
            Vt2[(4 * c4 + 2) * VP2 + kp] = make_float2(__uint_as_float(hh), __uint_as_float(ll));
            pack_bf16x3(vA.w, vB.w, hh, ll);
            Vt2[(4 * c4 + 3) * VP2 + kp] = make_float2(__uint_as_float(hh), __uint_as_float(ll));
        }
        __syncthreads();

        if (j * FBC > warp_rhi) continue;   // warp-uniform: fully masked tile

        // ---- S = Q K^T (bf16x3, m16n8k16): sacc[4 nt][4] ----
        float sacc[4][4];
#pragma unroll
        for (int nt = 0; nt < 4; nt++)
#pragma unroll
            for (int v = 0; v < 4; v++) sacc[nt][v] = 0.0f;

#pragma unroll
        for (int ks = 0; ks < 8; ks++) {
            const int k0 = ks * 16;      // dim base
            float2 qa0 = *(const float2*)&Qs[mrow * FQP + k0 + 2 * tg];
            float2 qa1 = *(const float2*)&Qs[(mrow + 8) * FQP + k0 + 2 * tg];
            float2 qa2 = *(const float2*)&Qs[mrow * FQP + k0 + 8 + 2 * tg];
            float2 qa3 = *(const float2*)&Qs[(mrow + 8) * FQP + k0 + 8 + 2 * tg];
            uint32_t ahi[4], alo[4];
            pack_bf16x3(qa0.x, qa0.y, ahi[0], alo[0]);
            pack_bf16x3(qa1.x, qa1.y, ahi[1], alo[1]);
            pack_bf16x3(qa2.x, qa2.y, ahi[2], alo[2]);
            pack_bf16x3(qa3.x, qa3.y, ahi[3], alo[3]);
#pragma unroll
            for (int nt = 0; nt < 4; nt++) {
                int n = nt * 8 + g;      // key within tile
                float2 f0 = Ks2[n * KP2 + k0 / 2 + tg];
                float2 f1 = Ks2[n * KP2 + k0 / 2 + 4 + tg];
                uint32_t bhi[2] = {__float_as_uint(f0.x), __float_as_uint(f1.x)};
                uint32_t blo[2] = {__float_as_uint(f0.y), __float_as_uint(f1.y)};
                mma_bf16(sacc[nt], ahi, bhi);
                mma_bf16(sacc[nt], ahi, blo);
                mma_bf16(sacc[nt], alo, bhi);
            }
        }

        // ---- causal mask on diagonal tiles ----
        if (j * FBC + FBC - 1 > r0g) {
#pragma unroll
            for (int nt = 0; nt < 4; nt++) {
                int c = j * FBC + nt * 8 + 2 * tg;
                if (c > r0g)     sacc[nt][0] = -1e30f;
                if (c + 1 > r0g) sacc[nt][1] = -1e30f;
                if (c > r1g)     sacc[nt][2] = -1e30f;
                if (c + 1 > r1g) sacc[nt][3] = -1e30f;
            }
        }

        // ---- online softmax in accumulator layout; P stays in regs ----
        float rmax0 = -1e30f, rmax1 = -1e30f;
#pragma unroll
        for (int nt = 0; nt < 4; nt++) {
            rmax0 = fmaxf(rmax0, fmaxf(sacc[nt][0], sacc[nt][1]));
            rmax1 = fmaxf(rmax1, fmaxf(sacc[nt][2], sacc[nt][3]));
        }
        rmax0 = fmaxf(rmax0, __shfl_xor_sync(0xffffffffu, rmax0, 1));
        rmax0 = fmaxf(rmax0, __shfl_xor_sync(0xffffffffu, rmax0, 2));
        rmax1 = fmaxf(rmax1, __shfl_xor_sync(0xffffffffu, rmax1, 1));
        rmax1 = fmaxf(rmax1, __shfl_xor_sync(0xffffffffu, rmax1, 2));

        float mn0 = fmaxf(m0, rmax0), mn1 = fmaxf(m1, rmax1);
        float alpha0 = __expf(m0 - mn0), alpha1 = __expf(m1 - mn1);

        float pex[4][4];
        float ps0 = 0.0f, ps1 = 0.0f;
#pragma unroll
        for (int nt = 0; nt < 4; nt++) {
            pex[nt][0] = __expf(sacc[nt][0] - mn0);
            pex[nt][1] = __expf(sacc[nt][1] - mn0);
            pex[nt][2] = __expf(sacc[nt][2] - mn1);
            pex[nt][3] = __expf(sacc[nt][3] - mn1);
            ps0 += pex[nt][0] + pex[nt][1];
            ps1 += pex[nt][2] + pex[nt][3];
        }
        ps0 += __shfl_xor_sync(0xffffffffu, ps0, 1);
        ps0 += __shfl_xor_sync(0xffffffffu, ps0, 2);
        ps1 += __shfl_xor_sync(0xffffffffu, ps1, 1);
        ps1 += __shfl_xor_sync(0xffffffffu, ps1, 2);

        l0 = l0 * alpha0 + ps0;  m0 = mn0;
        l1 = l1 * alpha1 + ps1;  m1 = mn1;

#pragma unroll
        for (int nt = 0; nt < 16; nt++) {
            O[nt][0] *= alpha0; O[nt][1] *= alpha0;
            O[nt][2] *= alpha1; O[nt][3] *= alpha1;
        }

        // ---- O += P V (bf16x3, m16n8k16; P packed from registers) ----
#pragma unroll
        for (int ks = 0; ks < 2; ks++) {
            uint32_t ahi[4], alo[4];
            pack_bf16x3(pex[2 * ks][0],     pex[2 * ks][1],     ahi[0], alo[0]);
            pack_bf16x3(pex[2 * ks][2],     pex[2 * ks][3],     ahi[1], alo[1]);
            pack_bf16x3(pex[2 * ks + 1][0], pex[2 * ks + 1][1], ahi[2], alo[2]);
            pack_bf16x3(pex[2 * ks + 1][2], pex[2 * ks + 1][3], ahi[3], alo[3]);
#pragma unroll
            for (int nt = 0; nt < 16; nt++) {
                int n = nt * 8 + g;      // dim
                float2 f0 = Vt2[n * VP2 + ks * 8 + tg];
                float2 f1 = Vt2[n * VP2 + ks * 8 + 4 + tg];
                uint32_t bhi[2] = {__float_as_uint(f0.x), __float_as_uint(f1.x)};
                uint32_t blo[2] = {__float_as_uint(f0.y), __float_as_uint(f1.y)};
                mma_bf16(O[nt], ahi, bhi);
                mma_bf16(O[nt], ahi, blo);
                mma_bf16(O[nt], alo, bhi);
            }
        }
    }

    // ---- epilogue: normalize and store ----
    float inv0 = 1.0f / l0, inv1 = 1.0f / l1;
#pragma unroll
    for (int nt = 0; nt < 16; nt++) {
        int c = nt * 8 + 2 * tg;
        *(float2*)&zb[(size_t)r0g * ldrow + c] =
            make_float2(O[nt][0] * inv0, O[nt][1] * inv0);
        *(float2*)&zb[(size_t)r1g * ldrow + c] =
            make_float2(O[nt][2] * inv1, O[nt][3] * inv1);
    }
}

// ---------------------------------------------------------------------------
// Launcher
// ---------------------------------------------------------------------------
extern "C" void kernel_launch(void* const* d_in, const int* in_sizes, int n_in,
                              void* d_out, int out_size)
{
    const float* xq = (const float*)d_in[0];
    const float* xk = (const float*)d_in[1];
    const float* xv = (const float*)d_in[2];
    const float* WQ = (const float*)d_in[3];
    const float* WK = (const float*)d_in[4];
    const float* WV = (const float*)d_in[5];
    const float* WO = (const float*)d_in[6];
    const float* bQ = (const float*)d_in[7];
    const float* bK = (const float*)d_in[8];
    const float* bV = (const float*)d_in[9];
    const float* bO = (const float*)d_in[10];
    float* out = (float*)d_out;

    float *qp, *kp, *vp, *zp;
    cudaGetSymbolAddress((void**)&qp, g_q);
    cudaGetSymbolAddress((void**)&kp, g_k);
    cudaGetSymbolAddress((void**)&vp, g_v);
    cudaGetSymbolAddress((void**)&zp, g_z);

    cudaFuncSetAttribute(qkv_gemm,
                         cudaFuncAttributeMaxDynamicSharedMemorySize, GEMM_SMEM);
    cudaFuncSetAttribute(out_gemm,
                         cudaFuncAttributeMaxDynamicSharedMemorySize, GEMM_SMEM);
    cudaFuncSetAttribute(flash_bf16_kernel,
                         cudaFuncAttributeMaxDynamicSharedMemorySize, FLASH3_SMEM);

    // Fused QKV projections: 32 x 16 x 3 CTAs in one launch
    dim3 gqkv(MROWS / 128, FEAT / 128, 3);
    qkv_gemm<<<gqkv, 256, GEMM_SMEM>>>(xq, xk, xv, WQ, WK, WV,
                                       bQ, bK, bV, qp, kp, vp);

    // Rotary on q and k
    rotary_kernel<<<16384, 256>>>(qp, kp);

    // Flash attention (bf16x3 tensor cores)
    flash_bf16_kernel<<<dim3(NS / 128, NH, NB), 256, FLASH3_SMEM>>>(qp, kp, vp, zp);

    // Output projection
    dim3 gout(MROWS / 128, FEAT / 128);
    out_gemm<<<gout, 256, GEMM_SMEM>>>(zp, WO, bO, out);
}